// round 3
// baseline (speedup 1.0000x reference)
#include <cuda_runtime.h>
#include <cuda_bf16.h>
#include <stdint.h>

// ---------------- problem dims ----------------
#define T_DIM   512
#define B_DIM   256
#define F_DIM   258
#define M_ROWS  (T_DIM * B_DIM)   // 131072
#define K0      256
#define H_DIM   1024

// ---------------- scratch (static device globals; allocation-free) ------------
__device__ __align__(16) __nv_bfloat16 g_Ahi[(size_t)M_ROWS * H_DIM];
__device__ __align__(16) __nv_bfloat16 g_Alo[(size_t)M_ROWS * H_DIM];
__device__ __align__(16) __nv_bfloat16 g_Bhi[(size_t)M_ROWS * H_DIM];
__device__ __align__(16) __nv_bfloat16 g_Blo[(size_t)M_ROWS * H_DIM];
__device__ __align__(16) __nv_bfloat16 g_W0hi[(size_t)H_DIM * K0];
__device__ __align__(16) __nv_bfloat16 g_W0lo[(size_t)H_DIM * K0];
__device__ __align__(16) __nv_bfloat16 g_W1hi[(size_t)H_DIM * H_DIM];
__device__ __align__(16) __nv_bfloat16 g_W1lo[(size_t)H_DIM * H_DIM];
__device__ __align__(16) __nv_bfloat16 g_W2hi[(size_t)H_DIM * H_DIM];
__device__ __align__(16) __nv_bfloat16 g_W2lo[(size_t)H_DIM * H_DIM];
__device__ float g_net[M_ROWS];

// ---------------- portable PTX helpers (compute_103-safe) ----------------
__device__ __forceinline__ uint32_t smem_u32(const void* p) {
    uint32_t a;
    asm("{ .reg .u64 t; cvta.to.shared.u64 t, %1; cvt.u32.u64 %0, t; }"
        : "=r"(a) : "l"(p));
    return a;
}

__device__ __forceinline__ void cpa16(uint32_t dst, const void* src) {
    asm volatile("cp.async.cg.shared.global [%0], [%1], 16;"
                 :: "r"(dst), "l"(src));
}
#define CP_COMMIT() asm volatile("cp.async.commit_group;" ::: "memory")
#define CP_WAIT1()  asm volatile("cp.async.wait_group 1;" ::: "memory")

#define LDSM_X4(r0, r1, r2, r3, addr) \
    asm volatile("ldmatrix.sync.aligned.m8n8.x4.shared.b16 {%0,%1,%2,%3}, [%4];" \
                 : "=r"(r0), "=r"(r1), "=r"(r2), "=r"(r3) : "r"(addr))

__device__ __forceinline__ void mma_bf16(float* c, const uint32_t* a, const uint32_t* b) {
    asm volatile(
        "mma.sync.aligned.m16n8k16.row.col.f32.bf16.bf16.f32 "
        "{%0,%1,%2,%3}, {%4,%5,%6,%7}, {%8,%9}, {%0,%1,%2,%3};"
        : "+f"(c[0]), "+f"(c[1]), "+f"(c[2]), "+f"(c[3])
        : "r"(a[0]), "r"(a[1]), "r"(a[2]), "r"(a[3]), "r"(b[0]), "r"(b[1]));
}

// swizzle: 128B rows, 16B chunk index ^= (row & 7). Apply to FINAL offset.
#define SWZ(off) ((off) ^ ((((off) >> 7) & 7) << 4))

// ---------------- kernel 1: pack features -> bf16 hi/lo ----------------
__global__ void pack_kernel(const float* __restrict__ u) {
    long idx = (long)blockIdx.x * blockDim.x + threadIdx.x;
    if (idx >= (long)M_ROWS * K0) return;
    int m = (int)(idx >> 8);
    int k = (int)(idx & 255);
    float v = u[(size_t)m * F_DIM + 2 + k];
    __nv_bfloat16 hi = __float2bfloat16(v);
    g_Ahi[(size_t)m * K0 + k] = hi;
    g_Alo[(size_t)m * K0 + k] = __float2bfloat16(v - __bfloat162float(hi));
}

// ---------------- kernel 2: weight transpose + split  W[K,N] -> Wt[N,K] ------
__global__ void wconv_kernel(const float* __restrict__ W, int K, int N,
                             __nv_bfloat16* __restrict__ Whi,
                             __nv_bfloat16* __restrict__ Wlo) {
    long idx = (long)blockIdx.x * blockDim.x + threadIdx.x;
    if (idx >= (long)K * N) return;
    int k = (int)(idx / N);
    int n = (int)(idx % N);
    float v = W[idx];                     // coalesced read
    __nv_bfloat16 hi = __float2bfloat16(v);
    Whi[(size_t)n * K + k] = hi;
    Wlo[(size_t)n * K + k] = __float2bfloat16(v - __bfloat162float(hi));
}

// ---------------- kernel 3: mma.sync GEMM, bf16x3 split --------------------
// CTA tile 128x128, K-chunk 64, 256 threads (8 warps as 4Mx2N, warp 32x64).
// smem per stage: Ahi | Alo | Bhi | Blo, each 128 rows x 128B (SWZ swizzled).
#define STG 65536
#define OFF_ALO 16384
#define OFF_BHI 32768
#define OFF_BLO 49152
#define GEMM_SMEM (2 * STG)

__global__ void __launch_bounds__(256, 1)
gemm_kernel(const __nv_bfloat16* __restrict__ Xhi, const __nv_bfloat16* __restrict__ Xlo,
            const __nv_bfloat16* __restrict__ Whi, const __nv_bfloat16* __restrict__ Wlo,
            const float* __restrict__ bias,
            __nv_bfloat16* __restrict__ Yhi, __nv_bfloat16* __restrict__ Ylo,
            int K, int N) {
    extern __shared__ __align__(1024) char smem[];
    const uint32_t sb = smem_u32(smem);

    const int tid = threadIdx.x;
    const int wid = tid >> 5;
    const int lid = tid & 31;
    const int wr  = wid >> 1;        // 0..3  (M)
    const int wc  = wid & 1;         // 0..1  (N)
    const int m0  = blockIdx.x * 128;
    const int n0  = blockIdx.y * 128;

    // ---- cp.async per-thread constants ----
    const int ldr = tid >> 3;                       // row low bits (0..31)
    const int ldc = tid & 7;                        // 16B chunk
    const uint32_t dst_base =
        (uint32_t)(ldr * 128 + ((ldc ^ (ldr & 7)) * 16));   // +it*4096
    const size_t kb = (size_t)K * 2;                // row bytes in global

    const char* gAh = (const char*)(Xhi + (size_t)m0 * K) + ldr * kb + ldc * 16;
    const char* gAl = (const char*)(Xlo + (size_t)m0 * K) + ldr * kb + ldc * 16;
    const char* gBh = (const char*)(Whi + (size_t)n0 * K) + ldr * kb + ldc * 16;
    const char* gBl = (const char*)(Wlo + (size_t)n0 * K) + ldr * kb + ldc * 16;

    // ---- ldmatrix per-lane UNswizzled base offsets (swizzle applied at use) ----
    // A tiles (mt=0,1): row = wr*32 + mt*16 + (lid&15), chunk base = (lid>>4)
    uint32_t abase[2];
#pragma unroll
    for (int mt = 0; mt < 2; mt++) {
        int r = wr * 32 + mt * 16 + (lid & 15);
        abase[mt] = (uint32_t)(r * 128 + (lid >> 4) * 16);
    }
    // B tile-pairs (ntp=0..3): row = wc*64 + ntp*16 + (lid&7) + ((lid>>4)&1)*8
    //                          chunk base = (lid>>3)&1
    uint32_t bbase[4];
#pragma unroll
    for (int ntp = 0; ntp < 4; ntp++) {
        int r = wc * 64 + ntp * 16 + (lid & 7) + ((lid >> 4) & 1) * 8;
        bbase[ntp] = (uint32_t)(r * 128 + ((lid >> 3) & 1) * 16);
    }

    float acc[2][8][4];
#pragma unroll
    for (int mt = 0; mt < 2; mt++)
#pragma unroll
        for (int nt = 0; nt < 8; nt++)
#pragma unroll
            for (int q = 0; q < 4; q++) acc[mt][nt][q] = 0.0f;

    const int nkc = K >> 6;          // K / 64

    // ---- issue one stage of loads ----
    auto issue = [&](int kc, int st) {
        uint32_t d = sb + st * STG + dst_base;
        size_t  go = (size_t)kc * 128;             // 64 bf16 = 128 bytes
#pragma unroll
        for (int it = 0; it < 4; it++) {
            uint32_t dd = d + it * 4096;
            size_t   gg = go + (size_t)it * 32 * kb;
            cpa16(dd,           gAh + gg);
            cpa16(dd + OFF_ALO, gAl + gg);
            cpa16(dd + OFF_BHI, gBh + gg);
            cpa16(dd + OFF_BLO, gBl + gg);
        }
        CP_COMMIT();
    };

    issue(0, 0);
    issue(1, 1);

    for (int kc = 0; kc < nkc; kc++) {
        CP_WAIT1();
        __syncthreads();

        const uint32_t s0 = sb + (kc & 1) * STG;
#pragma unroll
        for (int ks = 0; ks < 4; ks++) {
            uint32_t ah[2][4], al[2][4], bh[4][4], bl[4][4];
#pragma unroll
            for (int mt = 0; mt < 2; mt++) {
                uint32_t rel = SWZ(abase[mt] + ks * 32);
                LDSM_X4(ah[mt][0], ah[mt][1], ah[mt][2], ah[mt][3], s0 + rel);
                LDSM_X4(al[mt][0], al[mt][1], al[mt][2], al[mt][3],
                        s0 + OFF_ALO + rel);
            }
#pragma unroll
            for (int ntp = 0; ntp < 4; ntp++) {
                uint32_t rel = SWZ(bbase[ntp] + ks * 32);
                LDSM_X4(bh[ntp][0], bh[ntp][1], bh[ntp][2], bh[ntp][3],
                        s0 + OFF_BHI + rel);
                LDSM_X4(bl[ntp][0], bl[ntp][1], bl[ntp][2], bl[ntp][3],
                        s0 + OFF_BLO + rel);
            }
#pragma unroll
            for (int mt = 0; mt < 2; mt++) {
#pragma unroll
                for (int nt = 0; nt < 8; nt++) {
                    const uint32_t* bhp = &bh[nt >> 1][(nt & 1) * 2];
                    const uint32_t* blp = &bl[nt >> 1][(nt & 1) * 2];
                    mma_bf16(acc[mt][nt], ah[mt], bhp);   // Ah*Bh
                    mma_bf16(acc[mt][nt], al[mt], bhp);   // Al*Bh
                    mma_bf16(acc[mt][nt], ah[mt], blp);   // Ah*Bl
                }
            }
        }
        __syncthreads();
        if (kc + 2 < nkc) issue(kc + 2, kc & 1);
        else CP_COMMIT();                 // keep group count consistent
    }

    // ---- epilogue: bias + relu + re-split hi/lo ----
    const int erow = m0 + wr * 32 + (lid >> 2);
    const int ecol = n0 + wc * 64 + 2 * (lid & 3);
#pragma unroll
    for (int mt = 0; mt < 2; mt++) {
#pragma unroll
        for (int nt = 0; nt < 8; nt++) {
            const int col = ecol + nt * 8;
            const float bv0 = __ldg(&bias[col]);
            const float bv1 = __ldg(&bias[col + 1]);
#pragma unroll
            for (int h = 0; h < 2; h++) {     // h=0: row, h=1: row+8
                const int row = erow + mt * 16 + h * 8;
                float v0 = fmaxf(acc[mt][nt][2 * h]     + bv0, 0.0f);
                float v1 = fmaxf(acc[mt][nt][2 * h + 1] + bv1, 0.0f);
                __nv_bfloat16 h0 = __float2bfloat16(v0);
                __nv_bfloat16 h1 = __float2bfloat16(v1);
                __nv_bfloat16 l0 = __float2bfloat16(v0 - __bfloat162float(h0));
                __nv_bfloat16 l1 = __float2bfloat16(v1 - __bfloat162float(h1));
                *(__nv_bfloat162*)(Yhi + (size_t)row * N + col) =
                    __halves2bfloat162(h0, h1);
                *(__nv_bfloat162*)(Ylo + (size_t)row * N + col) =
                    __halves2bfloat162(l0, l1);
            }
        }
    }
}

// ---------------- kernel 4: final GEMV, folds b*c1 + b3 into net -------------
__global__ void gemv_kernel(const __nv_bfloat16* __restrict__ hi,
                            const __nv_bfloat16* __restrict__ lo,
                            const float* __restrict__ w3, const float* __restrict__ b3,
                            const float* __restrict__ u, const float* __restrict__ pb,
                            float* __restrict__ net) {
    const int wid = threadIdx.x >> 5, lid = threadIdx.x & 31;
    const int row = blockIdx.x * 8 + wid;
    const __nv_bfloat16* ph = hi + (size_t)row * H_DIM;
    const __nv_bfloat16* pl = lo + (size_t)row * H_DIM;
    float acc = 0.0f;
#pragma unroll 8
    for (int k = lid; k < H_DIM; k += 32) {
        float x = __bfloat162float(ph[k]) + __bfloat162float(pl[k]);
        acc = fmaf(x, __ldg(&w3[k]), acc);
    }
#pragma unroll
    for (int o = 16; o; o >>= 1) acc += __shfl_xor_sync(0xffffffffu, acc, o);
    if (lid == 0) {
        float c1 = u[(size_t)row * F_DIM + 1];
        net[row] = acc + b3[0] + (*pb) * c1;
    }
}

// ---------------- kernel 5: sequential scan ----------------
__global__ void scan_kernel(const float* __restrict__ u, const float* __restrict__ pa,
                            const float* __restrict__ net, float* __restrict__ out) {
    const int b = threadIdx.x;   // 256 threads
    const float a = *pa;
    float y = u[(size_t)b * F_DIM];          // u[0, b, 0]
    out[b] = y;
#pragma unroll 4
    for (int t = 0; t < T_DIM; t++) {
        y = a * y + net[t * B_DIM + b];
        out[(t + 1) * B_DIM + b] = y;
    }
}

// ---------------- launch ----------------
extern "C" void kernel_launch(void* const* d_in, const int* in_sizes, int n_in,
                              void* d_out, int out_size) {
    const float* u  = (const float*)d_in[0];
    const float* a  = (const float*)d_in[1];
    const float* b  = (const float*)d_in[2];
    const float* W0 = (const float*)d_in[3];
    const float* b0 = (const float*)d_in[4];
    const float* W1 = (const float*)d_in[5];
    const float* b1 = (const float*)d_in[6];
    const float* W2 = (const float*)d_in[7];
    const float* b2 = (const float*)d_in[8];
    const float* W3 = (const float*)d_in[9];
    const float* b3 = (const float*)d_in[10];
    float* out = (float*)d_out;

    void *pAhi, *pAlo, *pBhi, *pBlo;
    void *pW0h, *pW0l, *pW1h, *pW1l, *pW2h, *pW2l, *pNet;
    cudaGetSymbolAddress(&pAhi, g_Ahi);  cudaGetSymbolAddress(&pAlo, g_Alo);
    cudaGetSymbolAddress(&pBhi, g_Bhi);  cudaGetSymbolAddress(&pBlo, g_Blo);
    cudaGetSymbolAddress(&pW0h, g_W0hi); cudaGetSymbolAddress(&pW0l, g_W0lo);
    cudaGetSymbolAddress(&pW1h, g_W1hi); cudaGetSymbolAddress(&pW1l, g_W1lo);
    cudaGetSymbolAddress(&pW2h, g_W2hi); cudaGetSymbolAddress(&pW2l, g_W2lo);
    cudaGetSymbolAddress(&pNet, g_net);

    cudaFuncSetAttribute(gemm_kernel, cudaFuncAttributeMaxDynamicSharedMemorySize,
                         GEMM_SMEM);

    // 1. pack features (hi/lo)
    pack_kernel<<<(M_ROWS * K0) / 256, 256>>>(u);

    // 2. weight transpose + split
    wconv_kernel<<<(K0 * H_DIM) / 256, 256>>>(W0, K0, H_DIM,
        (__nv_bfloat16*)pW0h, (__nv_bfloat16*)pW0l);
    wconv_kernel<<<(H_DIM * H_DIM) / 256, 256>>>(W1, H_DIM, H_DIM,
        (__nv_bfloat16*)pW1h, (__nv_bfloat16*)pW1l);
    wconv_kernel<<<(H_DIM * H_DIM) / 256, 256>>>(W2, H_DIM, H_DIM,
        (__nv_bfloat16*)pW2h, (__nv_bfloat16*)pW2l);

    // 3. GEMMs: A(X0) -> B -> A -> B
    dim3 grid(M_ROWS / 128, H_DIM / 128);
    gemm_kernel<<<grid, 256, GEMM_SMEM>>>(
        (const __nv_bfloat16*)pAhi, (const __nv_bfloat16*)pAlo,
        (const __nv_bfloat16*)pW0h, (const __nv_bfloat16*)pW0l, b0,
        (__nv_bfloat16*)pBhi, (__nv_bfloat16*)pBlo, K0, H_DIM);
    gemm_kernel<<<grid, 256, GEMM_SMEM>>>(
        (const __nv_bfloat16*)pBhi, (const __nv_bfloat16*)pBlo,
        (const __nv_bfloat16*)pW1h, (const __nv_bfloat16*)pW1l, b1,
        (__nv_bfloat16*)pAhi, (__nv_bfloat16*)pAlo, H_DIM, H_DIM);
    gemm_kernel<<<grid, 256, GEMM_SMEM>>>(
        (const __nv_bfloat16*)pAhi, (const __nv_bfloat16*)pAlo,
        (const __nv_bfloat16*)pW2h, (const __nv_bfloat16*)pW2l, b2,
        (__nv_bfloat16*)pBhi, (__nv_bfloat16*)pBlo, H_DIM, H_DIM);

    // 4. GEMV (+ fold b*c1 + b3)
    gemv_kernel<<<M_ROWS / 8, 256>>>((const __nv_bfloat16*)pBhi,
                                     (const __nv_bfloat16*)pBlo, W3, b3,
                                     u, b, (float*)pNet);

    // 5. scan
    scan_kernel<<<1, 256>>>(u, a, (const float*)pNet, out);
}

// round 4
// speedup vs baseline: 2.7463x; 2.7463x over previous
#include <cuda_runtime.h>
#include <cuda_fp16.h>
#include <stdint.h>

// ---------------- problem dims ----------------
#define T_DIM   512
#define B_DIM   256
#define F_DIM   258
#define M_ROWS  (T_DIM * B_DIM)   // 131072
#define K0      256
#define H_DIM   1024

// ---------------- scratch (static device globals; allocation-free) ------------
__device__ __align__(16) __half g_A[(size_t)M_ROWS * H_DIM];
__device__ __align__(16) __half g_B[(size_t)M_ROWS * H_DIM];
__device__ __align__(16) __half g_W0[(size_t)H_DIM * K0];
__device__ __align__(16) __half g_W1[(size_t)H_DIM * H_DIM];
__device__ __align__(16) __half g_W2[(size_t)H_DIM * H_DIM];
__device__ float g_net[M_ROWS];

// ---------------- portable PTX helpers (compute_103-safe) ----------------
__device__ __forceinline__ uint32_t smem_u32(const void* p) {
    uint32_t a;
    asm("{ .reg .u64 t; cvta.to.shared.u64 t, %1; cvt.u32.u64 %0, t; }"
        : "=r"(a) : "l"(p));
    return a;
}

__device__ __forceinline__ void cpa16(uint32_t dst, const void* src) {
    asm volatile("cp.async.cg.shared.global [%0], [%1], 16;"
                 :: "r"(dst), "l"(src));
}
#define CP_COMMIT() asm volatile("cp.async.commit_group;" ::: "memory")
#define CP_WAIT1()  asm volatile("cp.async.wait_group 1;" ::: "memory")

#define LDSM_X4(r0, r1, r2, r3, addr) \
    asm volatile("ldmatrix.sync.aligned.m8n8.x4.shared.b16 {%0,%1,%2,%3}, [%4];" \
                 : "=r"(r0), "=r"(r1), "=r"(r2), "=r"(r3) : "r"(addr))

__device__ __forceinline__ void mma_f16(float* c, const uint32_t* a, const uint32_t* b) {
    asm volatile(
        "mma.sync.aligned.m16n8k16.row.col.f32.f16.f16.f32 "
        "{%0,%1,%2,%3}, {%4,%5,%6,%7}, {%8,%9}, {%0,%1,%2,%3};"
        : "+f"(c[0]), "+f"(c[1]), "+f"(c[2]), "+f"(c[3])
        : "r"(a[0]), "r"(a[1]), "r"(a[2]), "r"(a[3]), "r"(b[0]), "r"(b[1]));
}

// swizzle: 128B rows, 16B chunk index ^= (row & 7). Apply to FINAL offset.
#define SWZ(off) ((off) ^ ((((off) >> 7) & 7) << 4))

// ---------------- kernel 1: pack features -> fp16 ----------------
__global__ void pack_kernel(const float* __restrict__ u) {
    long idx = (long)blockIdx.x * blockDim.x + threadIdx.x;
    if (idx >= (long)M_ROWS * K0) return;
    int m = (int)(idx >> 8);
    int k = (int)(idx & 255);
    g_A[(size_t)m * K0 + k] = __float2half(u[(size_t)m * F_DIM + 2 + k]);
}

// ---------------- kernel 2: weight transpose + fp16  W[K,N] -> Wt[N,K] -------
__global__ void wconv_kernel(const float* __restrict__ W, int K, int N,
                             __half* __restrict__ Wt) {
    long idx = (long)blockIdx.x * blockDim.x + threadIdx.x;
    if (idx >= (long)K * N) return;
    int k = (int)(idx / N);
    int n = (int)(idx % N);
    Wt[(size_t)n * K + k] = __float2half(W[idx]);   // coalesced read
}

// ---------------- kernel 3: fp16 mma.sync GEMM -----------------------------
// CTA tile 128x128, K-chunk 64, 256 threads (8 warps as 4Mx2N, warp 32x64).
// 3-stage cp.async pipeline; stage = A(16KB) | B(16KB); 2 CTAs/SM.
#define STAGE  32768
#define OFF_B  16384
#define NSTG   3
#define GEMM_SMEM (NSTG * STAGE)

__global__ void __launch_bounds__(256, 2)
gemm_kernel(const __half* __restrict__ X, const __half* __restrict__ Wt,
            const float* __restrict__ bias, __half* __restrict__ Y,
            int K, int N) {
    extern __shared__ __align__(1024) char smem[];
    const uint32_t sb = smem_u32(smem);

    const int tid = threadIdx.x;
    const int wid = tid >> 5;
    const int lid = tid & 31;
    const int wr  = wid >> 1;        // 0..3  (M)
    const int wc  = wid & 1;         // 0..1  (N)
    const int n0  = blockIdx.x * 128;   // N fastest -> co-resident N-tiles share A
    const int m0  = blockIdx.y * 128;

    // ---- cp.async per-thread constants ----
    const int ldr = tid >> 3;                       // 0..31
    const int ldc = tid & 7;                        // 16B chunk
    const uint32_t dst_base =
        (uint32_t)(ldr * 128 + ((ldc ^ (ldr & 7)) * 16));   // +it*4096
    const size_t kb = (size_t)K * 2;                // row bytes in global

    const char* gA = (const char*)(X  + (size_t)m0 * K) + ldr * kb + ldc * 16;
    const char* gB = (const char*)(Wt + (size_t)n0 * K) + ldr * kb + ldc * 16;

    // ---- ldmatrix per-lane UNswizzled base offsets ----
    uint32_t abase[2];
#pragma unroll
    for (int mt = 0; mt < 2; mt++) {
        int r = wr * 32 + mt * 16 + (lid & 15);
        abase[mt] = (uint32_t)(r * 128 + (lid >> 4) * 16);
    }
    uint32_t bbase[4];
#pragma unroll
    for (int ntp = 0; ntp < 4; ntp++) {
        int r = wc * 64 + ntp * 16 + (lid & 7) + ((lid >> 4) & 1) * 8;
        bbase[ntp] = (uint32_t)(r * 128 + ((lid >> 3) & 1) * 16);
    }

    float acc[2][8][4];
#pragma unroll
    for (int mt = 0; mt < 2; mt++)
#pragma unroll
        for (int nt = 0; nt < 8; nt++)
#pragma unroll
            for (int q = 0; q < 4; q++) acc[mt][nt][q] = 0.0f;

    const int nkc = K >> 6;          // K / 64

    auto issue = [&](int kc, int st) {
        uint32_t d = sb + st * STAGE + dst_base;
        size_t  go = (size_t)kc * 128;             // 64 fp16 = 128 bytes
#pragma unroll
        for (int it = 0; it < 4; it++) {
            uint32_t dd = d + it * 4096;
            size_t   gg = go + (size_t)it * 32 * kb;
            cpa16(dd,         gA + gg);
            cpa16(dd + OFF_B, gB + gg);
        }
        CP_COMMIT();
    };

    issue(0, 0);
    if (nkc > 1) issue(1, 1); else CP_COMMIT();

    int st = 0;                      // stage of kc
    for (int kc = 0; kc < nkc; kc++) {
        CP_WAIT1();                  // group kc complete
        __syncthreads();             // also: all warps done with stage (kc+2)%3

        // prefetch kc+2 into the stage consumed at iter kc-1
        if (kc + 2 < nkc) {
            int st2 = st + 2; if (st2 >= NSTG) st2 -= NSTG;
            issue(kc + 2, st2);
        } else {
            CP_COMMIT();             // keep group count consistent
        }

        const uint32_t s0 = sb + st * STAGE;
#pragma unroll
        for (int ks = 0; ks < 4; ks++) {
            uint32_t ah[2][4], bh[4][4];
#pragma unroll
            for (int mt = 0; mt < 2; mt++) {
                uint32_t rel = SWZ(abase[mt] + ks * 32);
                LDSM_X4(ah[mt][0], ah[mt][1], ah[mt][2], ah[mt][3], s0 + rel);
            }
#pragma unroll
            for (int ntp = 0; ntp < 4; ntp++) {
                uint32_t rel = SWZ(bbase[ntp] + ks * 32);
                LDSM_X4(bh[ntp][0], bh[ntp][1], bh[ntp][2], bh[ntp][3],
                        s0 + OFF_B + rel);
            }
#pragma unroll
            for (int mt = 0; mt < 2; mt++) {
#pragma unroll
                for (int nt = 0; nt < 8; nt++) {
                    mma_f16(acc[mt][nt], ah[mt], &bh[nt >> 1][(nt & 1) * 2]);
                }
            }
        }
        if (++st == NSTG) st = 0;
    }

    // ---- epilogue: bias + relu -> fp16 ----
    const int erow = m0 + wr * 32 + (lid >> 2);
    const int ecol = n0 + wc * 64 + 2 * (lid & 3);
#pragma unroll
    for (int mt = 0; mt < 2; mt++) {
#pragma unroll
        for (int nt = 0; nt < 8; nt++) {
            const int col = ecol + nt * 8;
            const float bv0 = __ldg(&bias[col]);
            const float bv1 = __ldg(&bias[col + 1]);
#pragma unroll
            for (int h = 0; h < 2; h++) {     // h=0: row, h=1: row+8
                const int row = erow + mt * 16 + h * 8;
                float v0 = fmaxf(acc[mt][nt][2 * h]     + bv0, 0.0f);
                float v1 = fmaxf(acc[mt][nt][2 * h + 1] + bv1, 0.0f);
                *(__half2*)(Y + (size_t)row * N + col) =
                    __floats2half2_rn(v0, v1);
            }
        }
    }
}

// ---------------- kernel 4: final GEMV, folds b*c1 + b3 into net -------------
__global__ void gemv_kernel(const __half* __restrict__ h3,
                            const float* __restrict__ w3, const float* __restrict__ b3,
                            const float* __restrict__ u, const float* __restrict__ pb,
                            float* __restrict__ net) {
    const int wid = threadIdx.x >> 5, lid = threadIdx.x & 31;
    const int row = blockIdx.x * 8 + wid;
    const __half* ph = h3 + (size_t)row * H_DIM;
    float acc = 0.0f;
#pragma unroll
    for (int c = 0; c < 4; c++) {
        const int k = (c * 32 + lid) * 8;
        uint4 v = *(const uint4*)(ph + k);
        const __half2* hp = (const __half2*)&v;
#pragma unroll
        for (int j = 0; j < 4; j++) {
            float2 f = __half22float2(hp[j]);
            acc = fmaf(f.x, __ldg(&w3[k + 2 * j]),     acc);
            acc = fmaf(f.y, __ldg(&w3[k + 2 * j + 1]), acc);
        }
    }
#pragma unroll
    for (int o = 16; o; o >>= 1) acc += __shfl_xor_sync(0xffffffffu, acc, o);
    if (lid == 0) {
        float c1 = u[(size_t)row * F_DIM + 1];
        net[row] = acc + b3[0] + (*pb) * c1;
    }
}

// ---------------- kernel 5: sequential scan (8-wide batched loads) -----------
__global__ void scan_kernel(const float* __restrict__ u, const float* __restrict__ pa,
                            const float* __restrict__ net, float* __restrict__ out) {
    const int b = threadIdx.x;   // 256 threads
    const float a = *pa;
    float y = u[(size_t)b * F_DIM];          // u[0, b, 0]
    out[b] = y;
    for (int t = 0; t < T_DIM; t += 8) {
        float v[8];
#pragma unroll
        for (int j = 0; j < 8; j++) v[j] = net[(t + j) * B_DIM + b];
#pragma unroll
        for (int j = 0; j < 8; j++) {
            y = a * y + v[j];
            out[(t + 1 + j) * B_DIM + b] = y;
        }
    }
}

// ---------------- launch ----------------
extern "C" void kernel_launch(void* const* d_in, const int* in_sizes, int n_in,
                              void* d_out, int out_size) {
    const float* u  = (const float*)d_in[0];
    const float* a  = (const float*)d_in[1];
    const float* b  = (const float*)d_in[2];
    const float* W0 = (const float*)d_in[3];
    const float* b0 = (const float*)d_in[4];
    const float* W1 = (const float*)d_in[5];
    const float* b1 = (const float*)d_in[6];
    const float* W2 = (const float*)d_in[7];
    const float* b2 = (const float*)d_in[8];
    const float* W3 = (const float*)d_in[9];
    const float* b3 = (const float*)d_in[10];
    float* out = (float*)d_out;

    void *pA, *pB, *pW0, *pW1, *pW2, *pNet;
    cudaGetSymbolAddress(&pA, g_A);   cudaGetSymbolAddress(&pB, g_B);
    cudaGetSymbolAddress(&pW0, g_W0); cudaGetSymbolAddress(&pW1, g_W1);
    cudaGetSymbolAddress(&pW2, g_W2); cudaGetSymbolAddress(&pNet, g_net);

    cudaFuncSetAttribute(gemm_kernel, cudaFuncAttributeMaxDynamicSharedMemorySize,
                         GEMM_SMEM);

    // 1. pack features
    pack_kernel<<<(M_ROWS * K0) / 256, 256>>>(u);

    // 2. weight transpose
    wconv_kernel<<<(K0 * H_DIM) / 256, 256>>>(W0, K0, H_DIM, (__half*)pW0);
    wconv_kernel<<<(H_DIM * H_DIM) / 256, 256>>>(W1, H_DIM, H_DIM, (__half*)pW1);
    wconv_kernel<<<(H_DIM * H_DIM) / 256, 256>>>(W2, H_DIM, H_DIM, (__half*)pW2);

    // 3. GEMMs: A(X0) -> B -> A -> B    (grid.x = N-tiles for A reuse in L2)
    dim3 grid(H_DIM / 128, M_ROWS / 128);
    gemm_kernel<<<grid, 256, GEMM_SMEM>>>(
        (const __half*)pA, (const __half*)pW0, b0, (__half*)pB, K0, H_DIM);
    gemm_kernel<<<grid, 256, GEMM_SMEM>>>(
        (const __half*)pB, (const __half*)pW1, b1, (__half*)pA, H_DIM, H_DIM);
    gemm_kernel<<<grid, 256, GEMM_SMEM>>>(
        (const __half*)pA, (const __half*)pW2, b2, (__half*)pB, H_DIM, H_DIM);

    // 4. GEMV (+ fold b*c1 + b3)
    gemv_kernel<<<M_ROWS / 8, 256>>>((const __half*)pB, W3, b3, u, b, (float*)pNet);

    // 5. scan
    scan_kernel<<<1, 256>>>(u, a, (const float*)pNet, out);
}

// round 5
// speedup vs baseline: 2.8717x; 1.0457x over previous
#include <cuda_runtime.h>
#include <cuda_fp16.h>
#include <stdint.h>

// ---------------- problem dims ----------------
#define T_DIM   512
#define B_DIM   256
#define F_DIM   258
#define M_ROWS  (T_DIM * B_DIM)   // 131072
#define K0      256
#define H_DIM   1024

// ---------------- scratch (static device globals; allocation-free) ------------
__device__ __align__(16) __half g_A[(size_t)M_ROWS * H_DIM];
__device__ __align__(16) __half g_B[(size_t)M_ROWS * H_DIM];
__device__ __align__(16) __half g_W0[(size_t)H_DIM * K0];
__device__ __align__(16) __half g_W1[(size_t)H_DIM * H_DIM];
__device__ __align__(16) __half g_W2[(size_t)H_DIM * H_DIM];
__device__ float g_net[M_ROWS];

// ---------------- portable PTX helpers (compute_103-safe) ----------------
__device__ __forceinline__ uint32_t smem_u32(const void* p) {
    uint32_t a;
    asm("{ .reg .u64 t; cvta.to.shared.u64 t, %1; cvt.u32.u64 %0, t; }"
        : "=r"(a) : "l"(p));
    return a;
}

__device__ __forceinline__ void cpa16(uint32_t dst, const void* src) {
    asm volatile("cp.async.cg.shared.global [%0], [%1], 16;"
                 :: "r"(dst), "l"(src));
}
#define CP_COMMIT() asm volatile("cp.async.commit_group;" ::: "memory")
#define CP_WAIT1()  asm volatile("cp.async.wait_group 1;" ::: "memory")

#define LDSM_X4(r0, r1, r2, r3, addr) \
    asm volatile("ldmatrix.sync.aligned.m8n8.x4.shared.b16 {%0,%1,%2,%3}, [%4];" \
                 : "=r"(r0), "=r"(r1), "=r"(r2), "=r"(r3) : "r"(addr))

__device__ __forceinline__ void mma_f16(float* c, const uint32_t* a, const uint32_t* b) {
    asm volatile(
        "mma.sync.aligned.m16n8k16.row.col.f32.f16.f16.f32 "
        "{%0,%1,%2,%3}, {%4,%5,%6,%7}, {%8,%9}, {%0,%1,%2,%3};"
        : "+f"(c[0]), "+f"(c[1]), "+f"(c[2]), "+f"(c[3])
        : "r"(a[0]), "r"(a[1]), "r"(a[2]), "r"(a[3]), "r"(b[0]), "r"(b[1]));
}

// swizzle: 128B rows, 16B chunk index ^= (row & 7). Apply to FINAL offset.
#define SWZ(off) ((off) ^ ((((off) >> 7) & 7) << 4))

// ---------------- kernel 1: pack features -> fp16 ----------------
__global__ void pack_kernel(const float* __restrict__ u) {
    long idx = (long)blockIdx.x * blockDim.x + threadIdx.x;
    if (idx >= (long)M_ROWS * K0) return;
    int m = (int)(idx >> 8);
    int k = (int)(idx & 255);
    g_A[(size_t)m * K0 + k] = __float2half(u[(size_t)m * F_DIM + 2 + k]);
}

// ---------------- kernel 2: weight transpose + fp16  W[K,N] -> Wt[N,K] -------
__global__ void wconv_kernel(const float* __restrict__ W, int K, int N,
                             __half* __restrict__ Wt) {
    long idx = (long)blockIdx.x * blockDim.x + threadIdx.x;
    if (idx >= (long)K * N) return;
    int k = (int)(idx / N);
    int n = (int)(idx % N);
    Wt[(size_t)n * K + k] = __float2half(W[idx]);   // coalesced read
}

// ---------------- kernel 3: fp16 mma.sync GEMM -----------------------------
// CTA tile 128x128, K-chunk 64, 128 threads (4 warps as 2Mx2N, warp 64x64).
// 3-stage cp.async pipeline; stage = A(16KB) | B(16KB); 2 CTAs/SM.
#define STAGE  32768
#define OFF_B  16384
#define NSTG   3
#define GEMM_SMEM (NSTG * STAGE)

__global__ void __launch_bounds__(128, 2)
gemm_kernel(const __half* __restrict__ X, const __half* __restrict__ Wt,
            const float* __restrict__ bias, __half* __restrict__ Y,
            int K, int N) {
    extern __shared__ __align__(1024) char smem[];
    const uint32_t sb = smem_u32(smem);

    const int tid = threadIdx.x;
    const int wid = tid >> 5;        // 0..3
    const int lid = tid & 31;
    const int wr  = wid >> 1;        // 0..1  (M)
    const int wc  = wid & 1;         // 0..1  (N)
    const int n0  = blockIdx.x * 128;   // N fastest -> co-resident N-tiles share A
    const int m0  = blockIdx.y * 128;

    // ---- cp.async per-thread constants ----
    const int ldr = tid >> 3;                       // 0..15
    const int ldc = tid & 7;                        // 16B chunk
    const uint32_t dst_base =
        (uint32_t)(ldr * 128 + ((ldc ^ (ldr & 7)) * 16));   // +it*2048
    const size_t kb = (size_t)K * 2;                // row bytes in global

    const char* gA = (const char*)(X  + (size_t)m0 * K) + ldr * kb + ldc * 16;
    const char* gB = (const char*)(Wt + (size_t)n0 * K) + ldr * kb + ldc * 16;

    // ---- ldmatrix per-lane UNswizzled base offsets (swizzle applied at use) ----
    // A tiles (mt=0..3): row = wr*64 + mt*16 + (lid&15), chunk base = lid>>4
    uint32_t abase[4];
#pragma unroll
    for (int mt = 0; mt < 4; mt++) {
        int r = wr * 64 + mt * 16 + (lid & 15);
        abase[mt] = (uint32_t)(r * 128 + (lid >> 4) * 16);
    }
    // B tile-pairs (ntp=0..3): row = wc*64 + ntp*16 + (lid&7) + ((lid>>4)&1)*8
    uint32_t bbase[4];
#pragma unroll
    for (int ntp = 0; ntp < 4; ntp++) {
        int r = wc * 64 + ntp * 16 + (lid & 7) + ((lid >> 4) & 1) * 8;
        bbase[ntp] = (uint32_t)(r * 128 + ((lid >> 3) & 1) * 16);
    }

    float acc[4][8][4];
#pragma unroll
    for (int mt = 0; mt < 4; mt++)
#pragma unroll
        for (int nt = 0; nt < 8; nt++)
#pragma unroll
            for (int q = 0; q < 4; q++) acc[mt][nt][q] = 0.0f;

    const int nkc = K >> 6;          // K / 64

    auto issue = [&](int kc, int st) {
        uint32_t d = sb + st * STAGE + dst_base;
        size_t  go = (size_t)kc * 128;             // 64 fp16 = 128 bytes
#pragma unroll
        for (int it = 0; it < 8; it++) {
            uint32_t dd = d + it * 2048;
            size_t   gg = go + (size_t)it * 16 * kb;
            cpa16(dd,         gA + gg);
            cpa16(dd + OFF_B, gB + gg);
        }
        CP_COMMIT();
    };

    issue(0, 0);
    if (nkc > 1) issue(1, 1); else CP_COMMIT();

    int st = 0;                      // stage of kc
    for (int kc = 0; kc < nkc; kc++) {
        CP_WAIT1();                  // group kc complete
        __syncthreads();             // all warps done with stage (kc+2)%3

        if (kc + 2 < nkc) {
            int st2 = st + 2; if (st2 >= NSTG) st2 -= NSTG;
            issue(kc + 2, st2);
        } else {
            CP_COMMIT();             // keep group count consistent
        }

        const uint32_t s0 = sb + st * STAGE;
#pragma unroll
        for (int ks = 0; ks < 4; ks++) {
            uint32_t ah[4][4], bh[4][4];
#pragma unroll
            for (int mt = 0; mt < 4; mt++) {
                uint32_t rel = SWZ(abase[mt] + ks * 32);
                LDSM_X4(ah[mt][0], ah[mt][1], ah[mt][2], ah[mt][3], s0 + rel);
            }
#pragma unroll
            for (int ntp = 0; ntp < 4; ntp++) {
                uint32_t rel = SWZ(bbase[ntp] + ks * 32);
                LDSM_X4(bh[ntp][0], bh[ntp][1], bh[ntp][2], bh[ntp][3],
                        s0 + OFF_B + rel);
            }
#pragma unroll
            for (int mt = 0; mt < 4; mt++) {
#pragma unroll
                for (int nt = 0; nt < 8; nt++) {
                    mma_f16(acc[mt][nt], ah[mt], &bh[nt >> 1][(nt & 1) * 2]);
                }
            }
        }
        if (++st == NSTG) st = 0;
    }

    // ---- epilogue: bias + relu -> fp16 ----
    const int erow = m0 + wr * 64 + (lid >> 2);
    const int ecol = n0 + wc * 64 + 2 * (lid & 3);
#pragma unroll
    for (int mt = 0; mt < 4; mt++) {
#pragma unroll
        for (int nt = 0; nt < 8; nt++) {
            const int col = ecol + nt * 8;
            const float bv0 = __ldg(&bias[col]);
            const float bv1 = __ldg(&bias[col + 1]);
#pragma unroll
            for (int h = 0; h < 2; h++) {     // h=0: row, h=1: row+8
                const int row = erow + mt * 16 + h * 8;
                float v0 = fmaxf(acc[mt][nt][2 * h]     + bv0, 0.0f);
                float v1 = fmaxf(acc[mt][nt][2 * h + 1] + bv1, 0.0f);
                *(__half2*)(Y + (size_t)row * N + col) =
                    __floats2half2_rn(v0, v1);
            }
        }
    }
}

// ---------------- kernel 4: final GEMV, folds b*c1 + b3 into net -------------
__global__ void gemv_kernel(const __half* __restrict__ h3,
                            const float* __restrict__ w3, const float* __restrict__ b3,
                            const float* __restrict__ u, const float* __restrict__ pb,
                            float* __restrict__ net) {
    const int wid = threadIdx.x >> 5, lid = threadIdx.x & 31;
    const int row = blockIdx.x * 8 + wid;
    const __half* ph = h3 + (size_t)row * H_DIM;
    float acc = 0.0f;
#pragma unroll
    for (int c = 0; c < 4; c++) {
        const int k = (c * 32 + lid) * 8;
        uint4 v = *(const uint4*)(ph + k);
        const __half2* hp = (const __half2*)&v;
#pragma unroll
        for (int j = 0; j < 4; j++) {
            float2 f = __half22float2(hp[j]);
            acc = fmaf(f.x, __ldg(&w3[k + 2 * j]),     acc);
            acc = fmaf(f.y, __ldg(&w3[k + 2 * j + 1]), acc);
        }
    }
#pragma unroll
    for (int o = 16; o; o >>= 1) acc += __shfl_xor_sync(0xffffffffu, acc, o);
    if (lid == 0) {
        float c1 = u[(size_t)row * F_DIM + 1];
        net[row] = acc + b3[0] + (*pb) * c1;
    }
}

// ---------------- kernel 5: sequential scan (8-wide batched loads) -----------
__global__ void scan_kernel(const float* __restrict__ u, const float* __restrict__ pa,
                            const float* __restrict__ net, float* __restrict__ out) {
    const int b = threadIdx.x;   // 256 threads
    const float a = *pa;
    float y = u[(size_t)b * F_DIM];          // u[0, b, 0]
    out[b] = y;
    for (int t = 0; t < T_DIM; t += 8) {
        float v[8];
#pragma unroll
        for (int j = 0; j < 8; j++) v[j] = net[(t + j) * B_DIM + b];
#pragma unroll
        for (int j = 0; j < 8; j++) {
            y = a * y + v[j];
            out[(t + 1 + j) * B_DIM + b] = y;
        }
    }
}

// ---------------- launch ----------------
extern "C" void kernel_launch(void* const* d_in, const int* in_sizes, int n_in,
                              void* d_out, int out_size) {
    const float* u  = (const float*)d_in[0];
    const float* a  = (const float*)d_in[1];
    const float* b  = (const float*)d_in[2];
    const float* W0 = (const float*)d_in[3];
    const float* b0 = (const float*)d_in[4];
    const float* W1 = (const float*)d_in[5];
    const float* b1 = (const float*)d_in[6];
    const float* W2 = (const float*)d_in[7];
    const float* b2 = (const float*)d_in[8];
    const float* W3 = (const float*)d_in[9];
    const float* b3 = (const float*)d_in[10];
    float* out = (float*)d_out;

    void *pA, *pB, *pW0, *pW1, *pW2, *pNet;
    cudaGetSymbolAddress(&pA, g_A);   cudaGetSymbolAddress(&pB, g_B);
    cudaGetSymbolAddress(&pW0, g_W0); cudaGetSymbolAddress(&pW1, g_W1);
    cudaGetSymbolAddress(&pW2, g_W2); cudaGetSymbolAddress(&pNet, g_net);

    cudaFuncSetAttribute(gemm_kernel, cudaFuncAttributeMaxDynamicSharedMemorySize,
                         GEMM_SMEM);

    // 1. pack features
    pack_kernel<<<(M_ROWS * K0) / 256, 256>>>(u);

    // 2. weight transpose
    wconv_kernel<<<(K0 * H_DIM) / 256, 256>>>(W0, K0, H_DIM, (__half*)pW0);
    wconv_kernel<<<(H_DIM * H_DIM) / 256, 256>>>(W1, H_DIM, H_DIM, (__half*)pW1);
    wconv_kernel<<<(H_DIM * H_DIM) / 256, 256>>>(W2, H_DIM, H_DIM, (__half*)pW2);

    // 3. GEMMs: A(X0) -> B -> A -> B    (grid.x = N-tiles for A reuse in L2)
    dim3 grid(H_DIM / 128, M_ROWS / 128);
    gemm_kernel<<<grid, 128, GEMM_SMEM>>>(
        (const __half*)pA, (const __half*)pW0, b0, (__half*)pB, K0, H_DIM);
    gemm_kernel<<<grid, 128, GEMM_SMEM>>>(
        (const __half*)pB, (const __half*)pW1, b1, (__half*)pA, H_DIM, H_DIM);
    gemm_kernel<<<grid, 128, GEMM_SMEM>>>(
        (const __half*)pA, (const __half*)pW2, b2, (__half*)pB, H_DIM, H_DIM);

    // 4. GEMV (+ fold b*c1 + b3)
    gemv_kernel<<<M_ROWS / 8, 256>>>((const __half*)pB, W3, b3, u, b, (float*)pNet);

    // 5. scan
    scan_kernel<<<1, 256>>>(u, a, (const float*)pNet, out);
}

// round 6
// speedup vs baseline: 3.1347x; 1.0916x over previous
#include <cuda_runtime.h>
#include <cuda_fp16.h>
#include <stdint.h>

// ---------------- problem dims ----------------
#define T_DIM   512
#define B_DIM   256
#define F_DIM   258
#define M_ROWS  (T_DIM * B_DIM)   // 131072
#define K0      256
#define H_DIM   1024

// ---------------- scratch (static device globals; allocation-free) ------------
__device__ __align__(16) __half g_A[(size_t)M_ROWS * H_DIM];
__device__ __align__(16) __half g_B[(size_t)M_ROWS * H_DIM];
__device__ __align__(16) __half g_W0[(size_t)H_DIM * K0];
__device__ __align__(16) __half g_W1[(size_t)H_DIM * H_DIM];
__device__ __align__(16) __half g_W2[(size_t)H_DIM * H_DIM];
__device__ float g_net[M_ROWS];

// ---------------- portable PTX helpers (compute_103-safe) ----------------
__device__ __forceinline__ uint32_t smem_u32(const void* p) {
    uint32_t a;
    asm("{ .reg .u64 t; cvta.to.shared.u64 t, %1; cvt.u32.u64 %0, t; }"
        : "=r"(a) : "l"(p));
    return a;
}

__device__ __forceinline__ void cpa16(uint32_t dst, const void* src) {
    asm volatile("cp.async.cg.shared.global [%0], [%1], 16;"
                 :: "r"(dst), "l"(src));
}
#define CP_COMMIT() asm volatile("cp.async.commit_group;" ::: "memory")
#define CP_WAIT1()  asm volatile("cp.async.wait_group 1;" ::: "memory")

#define LDSM_X4(r0, r1, r2, r3, addr) \
    asm volatile("ldmatrix.sync.aligned.m8n8.x4.shared.b16 {%0,%1,%2,%3}, [%4];" \
                 : "=r"(r0), "=r"(r1), "=r"(r2), "=r"(r3) : "r"(addr))

__device__ __forceinline__ void mma_f16(float* c, const uint32_t* a, const uint32_t* b) {
    asm volatile(
        "mma.sync.aligned.m16n8k16.row.col.f32.f16.f16.f32 "
        "{%0,%1,%2,%3}, {%4,%5,%6,%7}, {%8,%9}, {%0,%1,%2,%3};"
        : "+f"(c[0]), "+f"(c[1]), "+f"(c[2]), "+f"(c[3])
        : "r"(a[0]), "r"(a[1]), "r"(a[2]), "r"(a[3]), "r"(b[0]), "r"(b[1]));
}

// swizzle: 128B rows, 16B chunk index ^= (row & 7). Apply to FINAL offset.
#define SWZ(off) ((off) ^ ((((off) >> 7) & 7) << 4))

// ---------------- kernel 1: pack features -> fp16 ----------------
__global__ void pack_kernel(const float* __restrict__ u) {
    long idx = (long)blockIdx.x * blockDim.x + threadIdx.x;
    if (idx >= (long)M_ROWS * K0) return;
    int m = (int)(idx >> 8);
    int k = (int)(idx & 255);
    g_A[(size_t)m * K0 + k] = __float2half(u[(size_t)m * F_DIM + 2 + k]);
}

// ---------------- kernel 1b: net init  net[m] = b3 + b*c1[m] ----------------
__global__ void netinit_kernel(const float* __restrict__ u,
                               const float* __restrict__ pb,
                               const float* __restrict__ b3) {
    int m = blockIdx.x * blockDim.x + threadIdx.x;
    if (m >= M_ROWS) return;
    g_net[m] = b3[0] + (*pb) * u[(size_t)m * F_DIM + 1];
}

// ---------------- kernel 2: weight transpose + fp16  W[K,N] -> Wt[N,K] -------
__global__ void wconv_kernel(const float* __restrict__ W, int K, int N,
                             __half* __restrict__ Wt) {
    long idx = (long)blockIdx.x * blockDim.x + threadIdx.x;
    if (idx >= (long)K * N) return;
    int k = (int)(idx / N);
    int n = (int)(idx % N);
    Wt[(size_t)n * K + k] = __float2half(W[idx]);   // coalesced read
}

// ---------------- kernel 3: fp16 mma.sync GEMM -----------------------------
// CTA tile 128x128, K-chunk 64, 128 threads (4 warps as 2Mx2N, warp 64x64).
// 3-stage cp.async pipeline; stage = A(16KB) | B(16KB); 2 CTAs/SM.
// If w3 != nullptr: instead of storing Y, reduce relu(acc+bias)*w3 into net.
#define STAGE  32768
#define OFF_B  16384
#define NSTG   3
#define GEMM_SMEM (NSTG * STAGE)

__global__ void __launch_bounds__(128, 2)
gemm_kernel(const __half* __restrict__ X, const __half* __restrict__ Wt,
            const float* __restrict__ bias, __half* __restrict__ Y,
            int K, int N,
            const float* __restrict__ w3, float* __restrict__ net) {
    extern __shared__ __align__(1024) char smem[];
    const uint32_t sb = smem_u32(smem);

    const int tid = threadIdx.x;
    const int wid = tid >> 5;        // 0..3
    const int lid = tid & 31;
    const int wr  = wid >> 1;        // 0..1  (M)
    const int wc  = wid & 1;         // 0..1  (N)
    const int n0  = blockIdx.x * 128;   // N fastest -> co-resident N-tiles share A
    const int m0  = blockIdx.y * 128;

    // ---- cp.async per-thread constants ----
    const int ldr = tid >> 3;                       // 0..15
    const int ldc = tid & 7;                        // 16B chunk
    const uint32_t dst_base =
        (uint32_t)(ldr * 128 + ((ldc ^ (ldr & 7)) * 16));   // +it*2048
    const size_t kb = (size_t)K * 2;                // row bytes in global

    const char* gA = (const char*)(X  + (size_t)m0 * K) + ldr * kb + ldc * 16;
    const char* gB = (const char*)(Wt + (size_t)n0 * K) + ldr * kb + ldc * 16;

    // ---- ldmatrix per-lane UNswizzled base offsets (swizzle applied at use) ----
    uint32_t abase[4];
#pragma unroll
    for (int mt = 0; mt < 4; mt++) {
        int r = wr * 64 + mt * 16 + (lid & 15);
        abase[mt] = (uint32_t)(r * 128 + (lid >> 4) * 16);
    }
    uint32_t bbase[4];
#pragma unroll
    for (int ntp = 0; ntp < 4; ntp++) {
        int r = wc * 64 + ntp * 16 + (lid & 7) + ((lid >> 4) & 1) * 8;
        bbase[ntp] = (uint32_t)(r * 128 + ((lid >> 3) & 1) * 16);
    }

    float acc[4][8][4];
#pragma unroll
    for (int mt = 0; mt < 4; mt++)
#pragma unroll
        for (int nt = 0; nt < 8; nt++)
#pragma unroll
            for (int q = 0; q < 4; q++) acc[mt][nt][q] = 0.0f;

    const int nkc = K >> 6;          // K / 64

    auto issue = [&](int kc, int st) {
        uint32_t d = sb + st * STAGE + dst_base;
        size_t  go = (size_t)kc * 128;             // 64 fp16 = 128 bytes
#pragma unroll
        for (int it = 0; it < 8; it++) {
            uint32_t dd = d + it * 2048;
            size_t   gg = go + (size_t)it * 16 * kb;
            cpa16(dd,         gA + gg);
            cpa16(dd + OFF_B, gB + gg);
        }
        CP_COMMIT();
    };

    issue(0, 0);
    if (nkc > 1) issue(1, 1); else CP_COMMIT();

    int st = 0;                      // stage of kc
    for (int kc = 0; kc < nkc; kc++) {
        CP_WAIT1();                  // group kc complete
        __syncthreads();             // all warps done with stage (kc+2)%3

        if (kc + 2 < nkc) {
            int st2 = st + 2; if (st2 >= NSTG) st2 -= NSTG;
            issue(kc + 2, st2);
        } else {
            CP_COMMIT();             // keep group count consistent
        }

        const uint32_t s0 = sb + st * STAGE;
#pragma unroll
        for (int ks = 0; ks < 4; ks++) {
            uint32_t ah[4][4], bh[4][4];
#pragma unroll
            for (int mt = 0; mt < 4; mt++) {
                uint32_t rel = SWZ(abase[mt] + ks * 32);
                LDSM_X4(ah[mt][0], ah[mt][1], ah[mt][2], ah[mt][3], s0 + rel);
            }
#pragma unroll
            for (int ntp = 0; ntp < 4; ntp++) {
                uint32_t rel = SWZ(bbase[ntp] + ks * 32);
                LDSM_X4(bh[ntp][0], bh[ntp][1], bh[ntp][2], bh[ntp][3],
                        s0 + OFF_B + rel);
            }
#pragma unroll
            for (int mt = 0; mt < 4; mt++) {
#pragma unroll
                for (int nt = 0; nt < 8; nt++) {
                    mma_f16(acc[mt][nt], ah[mt], &bh[nt >> 1][(nt & 1) * 2]);
                }
            }
        }
        if (++st == NSTG) st = 0;
    }

    const int erow = m0 + wr * 64 + (lid >> 2);
    const int ecol = n0 + wc * 64 + 2 * (lid & 3);

    if (w3 == nullptr) {
        // ---- epilogue A: bias + relu -> fp16 ----
#pragma unroll
        for (int mt = 0; mt < 4; mt++) {
#pragma unroll
            for (int nt = 0; nt < 8; nt++) {
                const int col = ecol + nt * 8;
                const float bv0 = __ldg(&bias[col]);
                const float bv1 = __ldg(&bias[col + 1]);
#pragma unroll
                for (int h = 0; h < 2; h++) {
                    const int row = erow + mt * 16 + h * 8;
                    float v0 = fmaxf(acc[mt][nt][2 * h]     + bv0, 0.0f);
                    float v1 = fmaxf(acc[mt][nt][2 * h + 1] + bv1, 0.0f);
                    *(__half2*)(Y + (size_t)row * N + col) =
                        __floats2half2_rn(v0, v1);
                }
            }
        }
    } else {
        // ---- epilogue B: fused final layer: net += relu(acc+bias) . w3 ----
#pragma unroll
        for (int mt = 0; mt < 4; mt++) {
#pragma unroll
            for (int h = 0; h < 2; h++) {
                float rs = 0.0f;
#pragma unroll
                for (int nt = 0; nt < 8; nt++) {
                    const int col = ecol + nt * 8;
                    float v0 = fmaxf(acc[mt][nt][2 * h]     + __ldg(&bias[col]),     0.0f);
                    float v1 = fmaxf(acc[mt][nt][2 * h + 1] + __ldg(&bias[col + 1]), 0.0f);
                    rs = fmaf(v0, __ldg(&w3[col]),     rs);
                    rs = fmaf(v1, __ldg(&w3[col + 1]), rs);
                }
                // quad-reduce across lid&3 (same row, disjoint cols)
                rs += __shfl_xor_sync(0xffffffffu, rs, 1);
                rs += __shfl_xor_sync(0xffffffffu, rs, 2);
                if ((lid & 3) == 0) {
                    const int row = erow + mt * 16 + h * 8;
                    atomicAdd(&net[row], rs);
                }
            }
        }
    }
}

// ---------------- kernel 5: sequential scan (8-wide batched loads) -----------
__global__ void scan_kernel(const float* __restrict__ u, const float* __restrict__ pa,
                            const float* __restrict__ net, float* __restrict__ out) {
    const int b = threadIdx.x;   // 256 threads
    const float a = *pa;
    float y = u[(size_t)b * F_DIM];          // u[0, b, 0]
    out[b] = y;
    for (int t = 0; t < T_DIM; t += 8) {
        float v[8];
#pragma unroll
        for (int j = 0; j < 8; j++) v[j] = net[(t + j) * B_DIM + b];
#pragma unroll
        for (int j = 0; j < 8; j++) {
            y = a * y + v[j];
            out[(t + 1 + j) * B_DIM + b] = y;
        }
    }
}

// ---------------- launch ----------------
extern "C" void kernel_launch(void* const* d_in, const int* in_sizes, int n_in,
                              void* d_out, int out_size) {
    const float* u  = (const float*)d_in[0];
    const float* a  = (const float*)d_in[1];
    const float* b  = (const float*)d_in[2];
    const float* W0 = (const float*)d_in[3];
    const float* b0 = (const float*)d_in[4];
    const float* W1 = (const float*)d_in[5];
    const float* b1 = (const float*)d_in[6];
    const float* W2 = (const float*)d_in[7];
    const float* b2 = (const float*)d_in[8];
    const float* W3 = (const float*)d_in[9];
    const float* b3 = (const float*)d_in[10];
    float* out = (float*)d_out;

    void *pA, *pB, *pW0, *pW1, *pW2, *pNet;
    cudaGetSymbolAddress(&pA, g_A);   cudaGetSymbolAddress(&pB, g_B);
    cudaGetSymbolAddress(&pW0, g_W0); cudaGetSymbolAddress(&pW1, g_W1);
    cudaGetSymbolAddress(&pW2, g_W2); cudaGetSymbolAddress(&pNet, g_net);

    cudaFuncSetAttribute(gemm_kernel, cudaFuncAttributeMaxDynamicSharedMemorySize,
                         GEMM_SMEM);

    // 1. pack features + init net = b3 + b*c1
    pack_kernel<<<(M_ROWS * K0) / 256, 256>>>(u);
    netinit_kernel<<<M_ROWS / 256, 256>>>(u, b, b3);

    // 2. weight transpose
    wconv_kernel<<<(K0 * H_DIM) / 256, 256>>>(W0, K0, H_DIM, (__half*)pW0);
    wconv_kernel<<<(H_DIM * H_DIM) / 256, 256>>>(W1, H_DIM, H_DIM, (__half*)pW1);
    wconv_kernel<<<(H_DIM * H_DIM) / 256, 256>>>(W2, H_DIM, H_DIM, (__half*)pW2);

    // 3. GEMMs: A(X0) -> B -> A -> net   (grid.x = N-tiles for A reuse in L2)
    dim3 grid(H_DIM / 128, M_ROWS / 128);
    gemm_kernel<<<grid, 128, GEMM_SMEM>>>(
        (const __half*)pA, (const __half*)pW0, b0, (__half*)pB, K0, H_DIM,
        nullptr, nullptr);
    gemm_kernel<<<grid, 128, GEMM_SMEM>>>(
        (const __half*)pB, (const __half*)pW1, b1, (__half*)pA, H_DIM, H_DIM,
        nullptr, nullptr);
    gemm_kernel<<<grid, 128, GEMM_SMEM>>>(
        (const __half*)pA, (const __half*)pW2, b2, (__half*)pB, H_DIM, H_DIM,
        W3, (float*)pNet);

    // 4. scan
    scan_kernel<<<1, 256>>>(u, a, (const float*)pNet, out);
}

// round 7
// speedup vs baseline: 3.2624x; 1.0407x over previous
#include <cuda_runtime.h>
#include <cuda_fp16.h>
#include <stdint.h>

// ---------------- problem dims ----------------
#define T_DIM   512
#define B_DIM   256
#define F_DIM   258
#define M_ROWS  (T_DIM * B_DIM)   // 131072
#define K0      256
#define H_DIM   1024

// ---------------- scratch (static device globals; allocation-free) ------------
__device__ __align__(16) __half g_A[(size_t)M_ROWS * H_DIM];
__device__ __align__(16) __half g_B[(size_t)M_ROWS * H_DIM];
__device__ __align__(16) __half g_W0[(size_t)H_DIM * K0];
__device__ __align__(16) __half g_W1[(size_t)H_DIM * H_DIM];
__device__ __align__(16) __half g_W2[(size_t)H_DIM * H_DIM];
__device__ float g_net[M_ROWS];

// ---------------- portable PTX helpers (compute_103-safe) ----------------
__device__ __forceinline__ uint32_t smem_u32(const void* p) {
    uint32_t a;
    asm("{ .reg .u64 t; cvta.to.shared.u64 t, %1; cvt.u32.u64 %0, t; }"
        : "=r"(a) : "l"(p));
    return a;
}

__device__ __forceinline__ void cpa16(uint32_t dst, const void* src) {
    asm volatile("cp.async.cg.shared.global [%0], [%1], 16;"
                 :: "r"(dst), "l"(src));
}
#define CP_COMMIT() asm volatile("cp.async.commit_group;" ::: "memory")
#define CP_WAIT1()  asm volatile("cp.async.wait_group 1;" ::: "memory")

#define LDSM_X4(r0, r1, r2, r3, addr) \
    asm volatile("ldmatrix.sync.aligned.m8n8.x4.shared.b16 {%0,%1,%2,%3}, [%4];" \
                 : "=r"(r0), "=r"(r1), "=r"(r2), "=r"(r3) : "r"(addr))

__device__ __forceinline__ void mma_f16(float* c, const uint32_t* a, const uint32_t* b) {
    asm volatile(
        "mma.sync.aligned.m16n8k16.row.col.f32.f16.f16.f32 "
        "{%0,%1,%2,%3}, {%4,%5,%6,%7}, {%8,%9}, {%0,%1,%2,%3};"
        : "+f"(c[0]), "+f"(c[1]), "+f"(c[2]), "+f"(c[3])
        : "r"(a[0]), "r"(a[1]), "r"(a[2]), "r"(a[3]), "r"(b[0]), "r"(b[1]));
}

// swizzle: 128B rows, 16B chunk index ^= (row & 7). Apply to FINAL offset.
#define SWZ(off) ((off) ^ ((((off) >> 7) & 7) << 4))

// ---------------- kernel 1: fused prep --------------------------------------
// blockIdx ranges:
//   [0, NB_PACK)                      : pack u features -> g_A (fp16)
//   [NB_PACK, +NB_W0+NB_W1+NB_W2)     : weight transpose+convert (smem tiles)
//   tail NB_NET blocks                : g_net = b3 + b*c1
#define NB_PACK  65536                 // 512 elems/block
#define NB_W0    256                   // (256/32)*(1024/32)
#define NB_W1    1024                  // (1024/32)^2
#define NB_W2    1024
#define NB_NET   256                   // 512 elems/block
#define NB_PREP  (NB_PACK + NB_W0 + NB_W1 + NB_W2 + NB_NET)

__global__ void __launch_bounds__(256)
prep_kernel(const float* __restrict__ u,
            const float* __restrict__ W0, const float* __restrict__ W1,
            const float* __restrict__ W2,
            const float* __restrict__ pb, const float* __restrict__ b3) {
    __shared__ __half s[32][33];
    int bid = blockIdx.x;
    const int tid = threadIdx.x;

    if (bid < NB_PACK) {
        // pack: 2 elems/thread, float2 read, half2 write
        long idx = ((long)bid * 256 + tid) * 2;
        int m = (int)(idx >> 8);
        int k = (int)(idx & 255);
        float2 v = *(const float2*)(u + (size_t)m * F_DIM + 2 + k);
        *(__half2*)(g_A + (size_t)m * K0 + k) = __floats2half2_rn(v.x, v.y);
        return;
    }
    bid -= NB_PACK;

    if (bid < NB_W0 + NB_W1 + NB_W2) {
        // transpose+convert one 32x32 tile: W[K,N] fp32 -> Wt[N,K] fp16
        const float* W; __half* Wt; int K, N, t;
        if (bid < NB_W0)              { W = W0; Wt = g_W0; K = K0;    N = H_DIM; t = bid; }
        else if (bid < NB_W0 + NB_W1) { W = W1; Wt = g_W1; K = H_DIM; N = H_DIM; t = bid - NB_W0; }
        else                          { W = W2; Wt = g_W2; K = H_DIM; N = H_DIM; t = bid - NB_W0 - NB_W1; }
        const int tn = t % (N >> 5), tk = t / (N >> 5);
        const int tx = tid & 31, ty = tid >> 5;        // 32 x 8
        const int k0 = tk * 32, n0 = tn * 32;
#pragma unroll
        for (int i = 0; i < 4; i++)
            s[ty + 8 * i][tx] = __float2half(W[(size_t)(k0 + ty + 8 * i) * N + n0 + tx]);
        __syncthreads();
#pragma unroll
        for (int i = 0; i < 4; i++)
            Wt[(size_t)(n0 + ty + 8 * i) * K + k0 + tx] = s[tx][ty + 8 * i];
        return;
    }
    bid -= NB_W0 + NB_W1 + NB_W2;

    // netinit: 2 elems/thread
    int m = (bid * 256 + tid) * 2;
    const float bb = *pb, bv = *b3;
    g_net[m]     = bv + bb * u[(size_t)m * F_DIM + 1];
    g_net[m + 1] = bv + bb * u[(size_t)(m + 1) * F_DIM + 1];
}

// ---------------- kernel 3: fp16 mma.sync GEMM -----------------------------
// CTA tile 128x128, K-chunk 64, 128 threads (4 warps as 2Mx2N, warp 64x64).
// 3-stage cp.async pipeline; stage = A(16KB) | B(16KB); 2 CTAs/SM.
// If w3 != nullptr: instead of storing Y, reduce relu(acc+bias)*w3 into net.
#define STAGE  32768
#define OFF_B  16384
#define NSTG   3
#define GEMM_SMEM (NSTG * STAGE)

__global__ void __launch_bounds__(128, 2)
gemm_kernel(const __half* __restrict__ X, const __half* __restrict__ Wt,
            const float* __restrict__ bias, __half* __restrict__ Y,
            int K, int N,
            const float* __restrict__ w3, float* __restrict__ net) {
    extern __shared__ __align__(1024) char smem[];
    const uint32_t sb = smem_u32(smem);

    const int tid = threadIdx.x;
    const int wid = tid >> 5;        // 0..3
    const int lid = tid & 31;
    const int wr  = wid >> 1;        // 0..1  (M)
    const int wc  = wid & 1;         // 0..1  (N)
    const int n0  = blockIdx.x * 128;   // N fastest -> co-resident N-tiles share A
    const int m0  = blockIdx.y * 128;

    // ---- cp.async per-thread constants ----
    const int ldr = tid >> 3;                       // 0..15
    const int ldc = tid & 7;                        // 16B chunk
    const uint32_t dst_base =
        (uint32_t)(ldr * 128 + ((ldc ^ (ldr & 7)) * 16));   // +it*2048
    const size_t kb = (size_t)K * 2;                // row bytes in global

    const char* gA = (const char*)(X  + (size_t)m0 * K) + ldr * kb + ldc * 16;
    const char* gB = (const char*)(Wt + (size_t)n0 * K) + ldr * kb + ldc * 16;

    // ---- ldmatrix per-lane UNswizzled base offsets (swizzle applied at use) ----
    uint32_t abase[4];
#pragma unroll
    for (int mt = 0; mt < 4; mt++) {
        int r = wr * 64 + mt * 16 + (lid & 15);
        abase[mt] = (uint32_t)(r * 128 + (lid >> 4) * 16);
    }
    uint32_t bbase[4];
#pragma unroll
    for (int ntp = 0; ntp < 4; ntp++) {
        int r = wc * 64 + ntp * 16 + (lid & 7) + ((lid >> 4) & 1) * 8;
        bbase[ntp] = (uint32_t)(r * 128 + ((lid >> 3) & 1) * 16);
    }

    float acc[4][8][4];
#pragma unroll
    for (int mt = 0; mt < 4; mt++)
#pragma unroll
        for (int nt = 0; nt < 8; nt++)
#pragma unroll
            for (int q = 0; q < 4; q++) acc[mt][nt][q] = 0.0f;

    const int nkc = K >> 6;          // K / 64

    auto issue = [&](int kc, int st) {
        uint32_t d = sb + st * STAGE + dst_base;
        size_t  go = (size_t)kc * 128;             // 64 fp16 = 128 bytes
#pragma unroll
        for (int it = 0; it < 8; it++) {
            uint32_t dd = d + it * 2048;
            size_t   gg = go + (size_t)it * 16 * kb;
            cpa16(dd,         gA + gg);
            cpa16(dd + OFF_B, gB + gg);
        }
        CP_COMMIT();
    };

    issue(0, 0);
    if (nkc > 1) issue(1, 1); else CP_COMMIT();

    int st = 0;                      // stage of kc
    for (int kc = 0; kc < nkc; kc++) {
        CP_WAIT1();                  // group kc complete
        __syncthreads();             // all warps done with stage (kc+2)%3

        if (kc + 2 < nkc) {
            int st2 = st + 2; if (st2 >= NSTG) st2 -= NSTG;
            issue(kc + 2, st2);
        } else {
            CP_COMMIT();             // keep group count consistent
        }

        const uint32_t s0 = sb + st * STAGE;
#pragma unroll
        for (int ks = 0; ks < 4; ks++) {
            uint32_t ah[4][4], bh[4][4];
#pragma unroll
            for (int mt = 0; mt < 4; mt++) {
                uint32_t rel = SWZ(abase[mt] + ks * 32);
                LDSM_X4(ah[mt][0], ah[mt][1], ah[mt][2], ah[mt][3], s0 + rel);
            }
#pragma unroll
            for (int ntp = 0; ntp < 4; ntp++) {
                uint32_t rel = SWZ(bbase[ntp] + ks * 32);
                LDSM_X4(bh[ntp][0], bh[ntp][1], bh[ntp][2], bh[ntp][3],
                        s0 + OFF_B + rel);
            }
#pragma unroll
            for (int mt = 0; mt < 4; mt++) {
#pragma unroll
                for (int nt = 0; nt < 8; nt++) {
                    mma_f16(acc[mt][nt], ah[mt], &bh[nt >> 1][(nt & 1) * 2]);
                }
            }
        }
        if (++st == NSTG) st = 0;
    }

    const int erow = m0 + wr * 64 + (lid >> 2);
    const int ecol = n0 + wc * 64 + 2 * (lid & 3);

    if (w3 == nullptr) {
        // ---- epilogue A: bias + relu -> fp16 ----
#pragma unroll
        for (int mt = 0; mt < 4; mt++) {
#pragma unroll
            for (int nt = 0; nt < 8; nt++) {
                const int col = ecol + nt * 8;
                const float bv0 = __ldg(&bias[col]);
                const float bv1 = __ldg(&bias[col + 1]);
#pragma unroll
                for (int h = 0; h < 2; h++) {
                    const int row = erow + mt * 16 + h * 8;
                    float v0 = fmaxf(acc[mt][nt][2 * h]     + bv0, 0.0f);
                    float v1 = fmaxf(acc[mt][nt][2 * h + 1] + bv1, 0.0f);
                    *(__half2*)(Y + (size_t)row * N + col) =
                        __floats2half2_rn(v0, v1);
                }
            }
        }
    } else {
        // ---- epilogue B: fused final layer: net += relu(acc+bias) . w3 ----
#pragma unroll
        for (int mt = 0; mt < 4; mt++) {
#pragma unroll
            for (int h = 0; h < 2; h++) {
                float rs = 0.0f;
#pragma unroll
                for (int nt = 0; nt < 8; nt++) {
                    const int col = ecol + nt * 8;
                    float v0 = fmaxf(acc[mt][nt][2 * h]     + __ldg(&bias[col]),     0.0f);
                    float v1 = fmaxf(acc[mt][nt][2 * h + 1] + __ldg(&bias[col + 1]), 0.0f);
                    rs = fmaf(v0, __ldg(&w3[col]),     rs);
                    rs = fmaf(v1, __ldg(&w3[col + 1]), rs);
                }
                // quad-reduce across lid&3 (same row, disjoint cols)
                rs += __shfl_xor_sync(0xffffffffu, rs, 1);
                rs += __shfl_xor_sync(0xffffffffu, rs, 2);
                if ((lid & 3) == 0) {
                    const int row = erow + mt * 16 + h * 8;
                    atomicAdd(&net[row], rs);
                }
            }
        }
    }
}

// ---------------- kernel 5: sequential scan (8-wide batched loads) -----------
__global__ void scan_kernel(const float* __restrict__ u, const float* __restrict__ pa,
                            const float* __restrict__ net, float* __restrict__ out) {
    const int b = threadIdx.x;   // 256 threads
    const float a = *pa;
    float y = u[(size_t)b * F_DIM];          // u[0, b, 0]
    out[b] = y;
    for (int t = 0; t < T_DIM; t += 8) {
        float v[8];
#pragma unroll
        for (int j = 0; j < 8; j++) v[j] = net[(t + j) * B_DIM + b];
#pragma unroll
        for (int j = 0; j < 8; j++) {
            y = a * y + v[j];
            out[(t + 1 + j) * B_DIM + b] = y;
        }
    }
}

// ---------------- launch ----------------
extern "C" void kernel_launch(void* const* d_in, const int* in_sizes, int n_in,
                              void* d_out, int out_size) {
    const float* u  = (const float*)d_in[0];
    const float* a  = (const float*)d_in[1];
    const float* b  = (const float*)d_in[2];
    const float* W0 = (const float*)d_in[3];
    const float* b0 = (const float*)d_in[4];
    const float* W1 = (const float*)d_in[5];
    const float* b1 = (const float*)d_in[6];
    const float* W2 = (const float*)d_in[7];
    const float* b2 = (const float*)d_in[8];
    const float* W3 = (const float*)d_in[9];
    const float* b3 = (const float*)d_in[10];
    float* out = (float*)d_out;

    void *pA, *pB, *pW0, *pW1, *pW2, *pNet;
    cudaGetSymbolAddress(&pA, g_A);   cudaGetSymbolAddress(&pB, g_B);
    cudaGetSymbolAddress(&pW0, g_W0); cudaGetSymbolAddress(&pW1, g_W1);
    cudaGetSymbolAddress(&pW2, g_W2); cudaGetSymbolAddress(&pNet, g_net);

    cudaFuncSetAttribute(gemm_kernel, cudaFuncAttributeMaxDynamicSharedMemorySize,
                         GEMM_SMEM);

    // 1. fused prep: pack + weight transposes + net init
    prep_kernel<<<NB_PREP, 256>>>(u, W0, W1, W2, b, b3);

    // 2. GEMMs: A(X0) -> B -> A -> net   (grid.x = N-tiles for A reuse in L2)
    dim3 grid(H_DIM / 128, M_ROWS / 128);
    gemm_kernel<<<grid, 128, GEMM_SMEM>>>(
        (const __half*)pA, (const __half*)pW0, b0, (__half*)pB, K0, H_DIM,
        nullptr, nullptr);
    gemm_kernel<<<grid, 128, GEMM_SMEM>>>(
        (const __half*)pB, (const __half*)pW1, b1, (__half*)pA, H_DIM, H_DIM,
        nullptr, nullptr);
    gemm_kernel<<<grid, 128, GEMM_SMEM>>>(
        (const __half*)pA, (const __half*)pW2, b2, (__half*)pB, H_DIM, H_DIM,
        W3, (float*)pNet);

    // 3. scan
    scan_kernel<<<1, 256>>>(u, a, (const float*)pNet, out);
}